// round 2
// baseline (speedup 1.0000x reference)
#include <cuda_runtime.h>
#include <cstdint>

// Scratch (no cudaMalloc allowed): row partial sums and per-(n,g) stats.
#define MAX_ROWS 16384
#define MAX_NG   4096
__device__ float g_rowsum[MAX_ROWS];
__device__ float g_rowsq[MAX_ROWS];
__device__ float g_mu[MAX_NG];
__device__ float g_ivar[MAX_NG];

// ---- int32/int64 robustness: values are small & nonzero (group sizes) or
// permutations of [0,8192) (indexes). For little-endian int64 buffers every
// odd 32-bit word is 0; for int32 buffers they are (w.h.p.) nonzero.
__device__ __forceinline__ bool buf_is_i64(const void* p) {
    const int* q = (const int*)p;
    return (q[1] == 0) && (q[3] == 0) && (q[5] == 0);
}
__device__ __forceinline__ long long load_i(const void* p, int i, bool is64) {
    return is64 ? ((const long long*)p)[i] : (long long)((const int*)p)[i];
}

// ---------------- Kernel 1: per permuted-row sum & sumsq ----------------
// One block per permuted row i (i = n*C + c). Gathers x row via indexes[i].
__global__ void __launch_bounds__(128) row_stats_kernel(
    const float* __restrict__ x,
    const void* __restrict__ indexes,
    int HW4)
{
    const int i = blockIdx.x;
    const bool is64 = buf_is_i64(indexes);
    const long long row = load_i(indexes, i, is64);
    const float4* __restrict__ p =
        (const float4*)(x + (size_t)row * (size_t)(HW4 * 4));

    float s1 = 0.f, s2 = 0.f;
    for (int j = threadIdx.x; j < HW4; j += blockDim.x) {
        float4 v = p[j];                 // normal load: populate L2 for pass 2
        s1 += (v.x + v.y) + (v.z + v.w);
        s2 += v.x * v.x + v.y * v.y + v.z * v.z + v.w * v.w;
    }

    // block reduce
    __shared__ float sh1[4], sh2[4];
    const int lane = threadIdx.x & 31, w = threadIdx.x >> 5;
    #pragma unroll
    for (int o = 16; o; o >>= 1) {
        s1 += __shfl_down_sync(0xffffffffu, s1, o);
        s2 += __shfl_down_sync(0xffffffffu, s2, o);
    }
    if (lane == 0) { sh1[w] = s1; sh2[w] = s2; }
    __syncthreads();
    if (threadIdx.x == 0) {
        float t1 = sh1[0] + sh1[1] + sh1[2] + sh1[3];
        float t2 = sh2[0] + sh2[1] + sh2[2] + sh2[3];
        g_rowsum[i] = t1;
        g_rowsq[i]  = t2;
    }
}

// ---------------- Kernel 2: per-(n, group) mean & inv-std ----------------
// grid = N*G blocks, 32 threads each.
__global__ void __launch_bounds__(32) group_stats_kernel(
    const void* __restrict__ group_sizes,
    int C, int G, int HW)
{
    const int b = blockIdx.x;
    const int n = b / G;
    const int g = b - n * G;
    const bool is64 = buf_is_i64(group_sizes);

    int cstart = 0;
    for (int k = 0; k < g; ++k) cstart += (int)load_i(group_sizes, k, is64);
    const int glen = (int)load_i(group_sizes, g, is64);

    float s1 = 0.f, s2 = 0.f;
    for (int c = threadIdx.x; c < glen; c += 32) {
        const int i = n * C + cstart + c;
        s1 += g_rowsum[i];
        s2 += g_rowsq[i];
    }
    #pragma unroll
    for (int o = 16; o; o >>= 1) {
        s1 += __shfl_down_sync(0xffffffffu, s1, o);
        s2 += __shfl_down_sync(0xffffffffu, s2, o);
    }
    if (threadIdx.x == 0) {
        const float cnt = (float)glen * (float)HW;
        const float mu  = s1 / cnt;
        const float var = (s2 - cnt * mu * mu) / (cnt - 1.0f);
        g_mu[b]   = mu;
        g_ivar[b] = rsqrtf(var + 1e-12f);
    }
}

// ---------------- Kernel 3: normalize + affine + scatter ----------------
// One block per permuted row. Writes to the SAME global row (indexes[i]),
// which is exactly the inverse permutation of the permuted result.
__global__ void __launch_bounds__(256) normalize_kernel(
    const float* __restrict__ x,
    float* __restrict__ out,
    const void* __restrict__ indexes,
    const float* __restrict__ weight,
    const float* __restrict__ bias,
    const void* __restrict__ group_sizes,
    int C, int G, int HW4)
{
    const int i = blockIdx.x;
    const int n = i / C;
    const int c = i - n * C;

    __shared__ float s_a, s_b;
    __shared__ long long s_row;
    if (threadIdx.x == 0) {
        const bool gs64 = buf_is_i64(group_sizes);
        // find group of permuted position c (G<=16, trivial scan)
        int g = 0, acc = 0;
        for (;;) {
            const int len = (int)load_i(group_sizes, g, gs64);
            if (c < acc + len) break;
            acc += len; ++g;
        }
        const int b = n * G + g;
        const float mu   = g_mu[b];
        const float ivar = g_ivar[b];
        const float wv   = weight[c];
        const float a    = ivar * wv;            // scale
        s_a = a;
        s_b = bias[c] - mu * a;                  // shift
        s_row = load_i(indexes, i, buf_is_i64(indexes));
    }
    __syncthreads();

    const float a = s_a, bsh = s_b;
    const size_t off = (size_t)s_row * (size_t)(HW4 * 4);
    const float4* __restrict__ px = (const float4*)(x + off);
    float4* __restrict__ po = (float4*)(out + off);

    for (int j = threadIdx.x; j < HW4; j += blockDim.x) {
        float4 v = __ldcs(&px[j]);               // last use: evict-first
        v.x = fmaf(v.x, a, bsh);
        v.y = fmaf(v.y, a, bsh);
        v.z = fmaf(v.z, a, bsh);
        v.w = fmaf(v.w, a, bsh);
        __stcs(&po[j], v);                       // streaming store
    }
}

extern "C" void kernel_launch(void* const* d_in, const int* in_sizes, int n_in,
                              void* d_out, int out_size)
{
    const float* x       = (const float*)d_in[0];
    const float* weight  = (const float*)d_in[1];
    const float* bias    = (const float*)d_in[2];
    const void*  gsizes  = d_in[3];
    const void*  indexes = d_in[4];
    // d_in[5] = reverse_indexes (unused: scatter via indexes is the inverse perm)
    float* out = (float*)d_out;

    const int C  = in_sizes[1];
    const int G  = in_sizes[3];
    const int NC = in_sizes[4];
    const int HW = in_sizes[0] / NC;
    const int HW4 = HW / 4;

    row_stats_kernel<<<NC, 128>>>(x, indexes, HW4);
    group_stats_kernel<<<(NC / C) * G, 32>>>(gsizes, C, G, HW);
    normalize_kernel<<<NC, 256>>>(x, out, indexes, weight, bias, gsizes, C, G, HW4);
}

// round 3
// speedup vs baseline: 1.0691x; 1.0691x over previous
#include <cuda_runtime.h>
#include <cstdint>

#define MAX_ROWS 16384
__device__ float g_rowsum[MAX_ROWS];
__device__ float g_rowsq[MAX_ROWS];

// ---- int32/int64 robustness: harness may deliver int64 refs as int32.
// For little-endian int64 buffers of small values every odd 32-bit word is 0.
__device__ __forceinline__ bool buf_is_i64(const void* p) {
    const int* q = (const int*)p;
    return (q[1] == 0) && (q[3] == 0) && (q[5] == 0);
}
__device__ __forceinline__ long long load_i(const void* p, int i, bool is64) {
    return is64 ? ((const long long*)p)[i] : (long long)((const int*)p)[i];
}

// ---------------- Kernel 1: per permuted-row sum & sumsq (warp per row) ----
__global__ void __launch_bounds__(256) row_stats_kernel(
    const float* __restrict__ x,
    const void* __restrict__ indexes,
    int HW4, int NC)
{
    const int warp = (blockIdx.x * (blockDim.x >> 5)) + (threadIdx.x >> 5);
    if (warp >= NC) return;
    const int lane = threadIdx.x & 31;
    const bool is64 = buf_is_i64(indexes);
    const long long row = load_i(indexes, warp, is64);
    const float4* __restrict__ p =
        (const float4*)(x + (size_t)row * (size_t)(HW4 * 4));

    float a1 = 0.f, a2 = 0.f, b1 = 0.f, b2 = 0.f;
    float c1 = 0.f, c2 = 0.f, d1 = 0.f, d2 = 0.f;
    const int nfull = (HW4 >> 7) << 7;           // multiple of 128
    for (int j0 = 0; j0 < nfull; j0 += 128) {
        float4 v0 = p[j0 + lane];
        float4 v1 = p[j0 + 32 + lane];
        float4 v2 = p[j0 + 64 + lane];
        float4 v3 = p[j0 + 96 + lane];
        a1 += (v0.x + v0.y) + (v0.z + v0.w);
        a2 += v0.x*v0.x + v0.y*v0.y + v0.z*v0.z + v0.w*v0.w;
        b1 += (v1.x + v1.y) + (v1.z + v1.w);
        b2 += v1.x*v1.x + v1.y*v1.y + v1.z*v1.z + v1.w*v1.w;
        c1 += (v2.x + v2.y) + (v2.z + v2.w);
        c2 += v2.x*v2.x + v2.y*v2.y + v2.z*v2.z + v2.w*v2.w;
        d1 += (v3.x + v3.y) + (v3.z + v3.w);
        d2 += v3.x*v3.x + v3.y*v3.y + v3.z*v3.z + v3.w*v3.w;
    }
    for (int j = nfull + lane; j < HW4; j += 32) {
        float4 v = p[j];
        a1 += (v.x + v.y) + (v.z + v.w);
        a2 += v.x*v.x + v.y*v.y + v.z*v.z + v.w*v.w;
    }
    float s1 = (a1 + b1) + (c1 + d1);
    float s2 = (a2 + b2) + (c2 + d2);
    #pragma unroll
    for (int o = 16; o; o >>= 1) {
        s1 += __shfl_down_sync(0xffffffffu, s1, o);
        s2 += __shfl_down_sync(0xffffffffu, s2, o);
    }
    if (lane == 0) { g_rowsum[warp] = s1; g_rowsq[warp] = s2; }
}

// ---------------- Kernel 2: normalize + affine + scatter (warp per row) ----
// Each warp recomputes its group's stats inline (<=1us total, L2-resident)
// and streams its row: out[indexes[i]] = a*x[indexes[i]] + b.
__global__ void __launch_bounds__(256) normalize_kernel(
    const float* __restrict__ x,
    float* __restrict__ out,
    const void* __restrict__ indexes,
    const float* __restrict__ weight,
    const float* __restrict__ bias,
    const void* __restrict__ group_sizes,
    int C, int G, int HW4, int NC)
{
    const int i = (blockIdx.x * (blockDim.x >> 5)) + (threadIdx.x >> 5);
    if (i >= NC) return;
    const int lane = threadIdx.x & 31;
    const int n = i / C;
    const int c = i - n * C;

    // --- warp-scan group boundaries (G <= 32) ---
    const bool gs64 = buf_is_i64(group_sizes);
    int gsz = (lane < G) ? (int)load_i(group_sizes, lane, gs64) : 0;
    int scan = gsz;
    #pragma unroll
    for (int o = 1; o < 32; o <<= 1) {
        int t = __shfl_up_sync(0xffffffffu, scan, o);
        if (lane >= o) scan += t;
    }
    const int gstart_l = scan - gsz;             // start of group 'lane'
    const unsigned m = __ballot_sync(0xffffffffu,
                                     (lane < G) && (c >= gstart_l) && (c < scan));
    const int g      = __ffs(m) - 1;
    const int cstart = __shfl_sync(0xffffffffu, gstart_l, g);
    const int glen   = __shfl_sync(0xffffffffu, gsz, g);

    // --- group stats from row partials ---
    float s1 = 0.f, s2 = 0.f;
    for (int cc = lane; cc < glen; cc += 32) {
        const int r = n * C + cstart + cc;
        s1 += g_rowsum[r];
        s2 += g_rowsq[r];
    }
    #pragma unroll
    for (int o = 16; o; o >>= 1) {               // xor-reduce: all lanes get it
        s1 += __shfl_xor_sync(0xffffffffu, s1, o);
        s2 += __shfl_xor_sync(0xffffffffu, s2, o);
    }
    const float cnt  = (float)glen * (float)(HW4 * 4);
    const float mu   = s1 / cnt;
    const float var  = (s2 - cnt * mu * mu) / (cnt - 1.0f);
    const float ivar = rsqrtf(var + 1e-12f);
    const float a    = ivar * weight[c];
    const float bsh  = bias[c] - mu * a;

    const long long row = load_i(indexes, i, buf_is_i64(indexes));
    const size_t off = (size_t)row * (size_t)(HW4 * 4);
    const float4* __restrict__ px = (const float4*)(x + off);
    float4*       __restrict__ po = (float4*)(out + off);

    const int nfull = (HW4 >> 7) << 7;
    for (int j0 = 0; j0 < nfull; j0 += 128) {
        float4 v0 = __ldcs(&px[j0 + lane]);
        float4 v1 = __ldcs(&px[j0 + 32 + lane]);
        float4 v2 = __ldcs(&px[j0 + 64 + lane]);
        float4 v3 = __ldcs(&px[j0 + 96 + lane]);
        v0.x = fmaf(v0.x, a, bsh); v0.y = fmaf(v0.y, a, bsh);
        v0.z = fmaf(v0.z, a, bsh); v0.w = fmaf(v0.w, a, bsh);
        v1.x = fmaf(v1.x, a, bsh); v1.y = fmaf(v1.y, a, bsh);
        v1.z = fmaf(v1.z, a, bsh); v1.w = fmaf(v1.w, a, bsh);
        v2.x = fmaf(v2.x, a, bsh); v2.y = fmaf(v2.y, a, bsh);
        v2.z = fmaf(v2.z, a, bsh); v2.w = fmaf(v2.w, a, bsh);
        v3.x = fmaf(v3.x, a, bsh); v3.y = fmaf(v3.y, a, bsh);
        v3.z = fmaf(v3.z, a, bsh); v3.w = fmaf(v3.w, a, bsh);
        __stcs(&po[j0 + lane], v0);
        __stcs(&po[j0 + 32 + lane], v1);
        __stcs(&po[j0 + 64 + lane], v2);
        __stcs(&po[j0 + 96 + lane], v3);
    }
    for (int j = nfull + lane; j < HW4; j += 32) {
        float4 v = __ldcs(&px[j]);
        v.x = fmaf(v.x, a, bsh); v.y = fmaf(v.y, a, bsh);
        v.z = fmaf(v.z, a, bsh); v.w = fmaf(v.w, a, bsh);
        __stcs(&po[j], v);
    }
}

extern "C" void kernel_launch(void* const* d_in, const int* in_sizes, int n_in,
                              void* d_out, int out_size)
{
    const float* x       = (const float*)d_in[0];
    const float* weight  = (const float*)d_in[1];
    const float* bias    = (const float*)d_in[2];
    const void*  gsizes  = d_in[3];
    const void*  indexes = d_in[4];
    float* out = (float*)d_out;

    const int C   = in_sizes[1];
    const int G   = in_sizes[3];
    const int NC  = in_sizes[4];
    const int HW  = in_sizes[0] / NC;
    const int HW4 = HW / 4;

    const int WPB = 256 / 32;                    // warps per block
    const int grid = (NC + WPB - 1) / WPB;
    row_stats_kernel<<<grid, 256>>>(x, indexes, HW4, NC);
    normalize_kernel<<<grid, 256>>>(x, out, indexes, weight, bias, gsizes,
                                    C, G, HW4, NC);
}